// round 7
// baseline (speedup 1.0000x reference)
#include <cuda_runtime.h>
#include <cstdint>

#define N_NODES 100000
#define N_EDGES 1250000
#define F 64
#define K_DIM 128

// ---------------- device scratch ----------------
__device__ int g_count[N_NODES];     // in-degree (zeroed by gemm tail each replay)
__device__ int g_cursor[N_NODES];    // block-LOCAL excl offset; fill bumps it
__device__ int g_esrc[N_EDGES];      // src ids grouped by dst (global CSR order)

#define SCAN_BLOCK 1024
#define SCAN_NBLK ((N_NODES + SCAN_BLOCK - 1) / SCAN_BLOCK)   // 98
__device__ int g_bsum[SCAN_NBLK];    // per-scan-block edge totals

// ---------------------------------------------------------------------------
// 1) histogram of dst, 4 edges/thread. (g_count arrives zeroed: static init on
//    first call, gemm-tail zeroing on every subsequent replay.)
// ---------------------------------------------------------------------------
__global__ void hist_kernel(const int* __restrict__ dst) {
    int i = blockIdx.x * blockDim.x + threadIdx.x;
    if (i >= N_EDGES / 4) return;
    int4 d = ((const int4*)dst)[i];
    if ((unsigned)d.x < N_NODES) atomicAdd(&g_count[d.x], 1);
    if ((unsigned)d.y < N_NODES) atomicAdd(&g_count[d.y], 1);
    if ((unsigned)d.z < N_NODES) atomicAdd(&g_count[d.z], 1);
    if ((unsigned)d.w < N_NODES) atomicAdd(&g_count[d.w], 1);
}

// ---------------------------------------------------------------------------
// 2) block-local exclusive scan -> g_cursor (local offsets), totals -> g_bsum.
//    No cross-block communication; strictly terminating.
// ---------------------------------------------------------------------------
__global__ __launch_bounds__(SCAN_BLOCK) void scan1_kernel() {
    __shared__ int wsum[32];
    int tid = threadIdx.x;
    int lane = tid & 31, wid = tid >> 5;
    int i = blockIdx.x * SCAN_BLOCK + tid;
    int v = (i < N_NODES) ? g_count[i] : 0;

    int inc = v;
#pragma unroll
    for (int d = 1; d < 32; d <<= 1) {
        int t = __shfl_up_sync(0xffffffffu, inc, d);
        if (lane >= d) inc += t;
    }
    if (lane == 31) wsum[wid] = inc;
    __syncthreads();
    if (wid == 0) {
        int wv = wsum[lane];
        int winc = wv;
#pragma unroll
        for (int d = 1; d < 32; d <<= 1) {
            int t = __shfl_up_sync(0xffffffffu, winc, d);
            if (lane >= d) winc += t;
        }
        wsum[lane] = winc - wv;
    }
    __syncthreads();
    int excl = (inc - v) + wsum[wid];
    if (i < N_NODES) g_cursor[i] = excl;              // block-LOCAL offset
    if (tid == SCAN_BLOCK - 1) g_bsum[blockIdx.x] = excl + v;
}

// ---------------------------------------------------------------------------
// 3) bucket fill, 4 edges/thread. Each block reconstructs the 98-entry
//    cross-scan-block exclusive prefix in smem (cheap, amortized).
//    global pos = prefix[d>>10] + atomicAdd(local cursor).
// ---------------------------------------------------------------------------
__global__ __launch_bounds__(256) void fill_kernel(const int* __restrict__ src,
                                                   const int* __restrict__ dst) {
    __shared__ int sb[SCAN_NBLK];
    __shared__ int sp[SCAN_NBLK];
    int tid = threadIdx.x;
    if (tid < SCAN_NBLK) sb[tid] = g_bsum[tid];
    __syncthreads();
    if (tid < SCAN_NBLK) {
        int a = 0;
        for (int j = 0; j < tid; j++) a += sb[j];
        sp[tid] = a;
    }
    __syncthreads();

    int i = blockIdx.x * blockDim.x + tid;
    if (i >= N_EDGES / 4) return;
    int4 s4 = ((const int4*)src)[i];
    int4 d4 = ((const int4*)dst)[i];
#pragma unroll
    for (int j = 0; j < 4; j++) {
        int d = (j == 0) ? d4.x : (j == 1) ? d4.y : (j == 2) ? d4.z : d4.w;
        int s = (j == 0) ? s4.x : (j == 1) ? s4.y : (j == 2) ? s4.z : s4.w;
        if ((unsigned)d < N_NODES) {
            int pos = sp[d >> 10] + atomicAdd(&g_cursor[d], 1);
            if ((unsigned)pos < N_EDGES)
                g_esrc[pos] = ((unsigned)s < N_NODES) ? s : 0;
        }
    }
}

// ---------------------------------------------------------------------------
// 4) fused aggregate + tensor-core GEMM (3xTF32 split) + g_count re-zero.
//    Node start offset = base(blk) + g_cursor[node] - g_count[node]
//    (cursor ended at local_excl + deg after fill).
// ---------------------------------------------------------------------------
#define NT 64
#define GSTR 132
#define GEMM_SMEM_BYTES (3 * 64 * GSTR * 4)   // Xs + Whi + Wlo = 101,376 B

__device__ __forceinline__ void split_tf32(float x, unsigned& hi, unsigned& lo) {
    unsigned h;
    asm("cvt.rna.tf32.f32 %0, %1;" : "=r"(h) : "f"(x));
    float r = x - __uint_as_float(h);
    asm("cvt.rna.tf32.f32 %0, %1;" : "=r"(lo) : "f"(r));
    hi = h;
}

__device__ __forceinline__ void mma_tf32(float d[4], const unsigned a[4],
                                         unsigned b0, unsigned b1) {
    asm volatile(
        "mma.sync.aligned.m16n8k8.row.col.f32.tf32.tf32.f32 "
        "{%0,%1,%2,%3}, {%4,%5,%6,%7}, {%8,%9}, {%0,%1,%2,%3};\n"
        : "+f"(d[0]), "+f"(d[1]), "+f"(d[2]), "+f"(d[3])
        : "r"(a[0]), "r"(a[1]), "r"(a[2]), "r"(a[3]), "r"(b0), "r"(b1));
}

__global__ __launch_bounds__(128) void gemm_kernel(const float* __restrict__ h,
                                                   const float* __restrict__ W,
                                                   const float* __restrict__ b,
                                                   float* __restrict__ out) {
    extern __shared__ float smem[];
    float* Xs  = smem;                  // [64][GSTR]
    float* Whi = smem + 64 * GSTR;      // [64][GSTR] tf32 bits
    float* Wlo = smem + 2 * 64 * GSTR;  // [64][GSTR] tf32 bits

    int tid = threadIdx.x;
    int node0 = blockIdx.x * NT;

    // cross-scan-block base for this block's nodes (all 64 share one scan blk)
    int blk = node0 >> 10;
    int base = 0;
    for (int j = 0; j < blk; j++) base += g_bsum[j];   // uniform broadcast loads

    // --- Phase A1: W load + one-time tf32 split ---
    for (int idx = tid; idx < 64 * K_DIM; idx += 128) {
        int o = idx >> 7, k = idx & 127;
        float w = W[idx];
        unsigned hi, lo;
        split_tf32(w, hi, lo);
        Whi[o * GSTR + k] = __uint_as_float(hi);
        Wlo[o * GSTR + k] = __uint_as_float(lo);
    }

    // --- Phase A2: self features ---
    for (int idx = tid; idx < NT * 16; idx += 128) {
        int n = idx >> 4, q = idx & 15;
        int node = node0 + n;
        float4 v = make_float4(0.f, 0.f, 0.f, 0.f);
        if (node < N_NODES) v = ((const float4*)(h + (long long)node * F))[q];
        *(float4*)&Xs[n * GSTR + q * 4] = v;
    }

    // --- Phase A3: neighbor mean, half-warp per node ---
    {
        int hw = tid >> 4;
        int ln = tid & 15;
        for (int n = hw; n < NT; n += 8) {
            int node = node0 + n;
            float4 a = make_float4(0.f, 0.f, 0.f, 0.f);
            float inv = 0.f;
            if (node < N_NODES) {
                int deg = g_count[node];
                int off = base + g_cursor[node] - deg;
                int e = 0;
                for (; e + 4 <= deg; e += 4) {
                    int s0 = g_esrc[off + e + 0];
                    int s1 = g_esrc[off + e + 1];
                    int s2 = g_esrc[off + e + 2];
                    int s3 = g_esrc[off + e + 3];
                    float4 v0 = ((const float4*)(h + (long long)s0 * F))[ln];
                    float4 v1 = ((const float4*)(h + (long long)s1 * F))[ln];
                    float4 v2 = ((const float4*)(h + (long long)s2 * F))[ln];
                    float4 v3 = ((const float4*)(h + (long long)s3 * F))[ln];
                    a.x += v0.x + v1.x + v2.x + v3.x;
                    a.y += v0.y + v1.y + v2.y + v3.y;
                    a.z += v0.z + v1.z + v2.z + v3.z;
                    a.w += v0.w + v1.w + v2.w + v3.w;
                }
                for (; e < deg; e++) {
                    int s = g_esrc[off + e];
                    float4 v = ((const float4*)(h + (long long)s * F))[ln];
                    a.x += v.x; a.y += v.y; a.z += v.z; a.w += v.w;
                }
                inv = 1.f / fmaxf((float)deg, 1.f);
            }
            *(float4*)&Xs[n * GSTR + 64 + ln * 4] =
                make_float4(a.x * inv, a.y * inv, a.z * inv, a.w * inv);
        }
    }
    __syncthreads();

    // --- tail: re-zero this block's g_count for the next replay ---
    // (safe: all reads of g_count happened before the barrier; no other block
    //  touches these nodes)
    for (int n = tid; n < NT; n += 128) {
        int node = node0 + n;
        if (node < N_NODES) g_count[node] = 0;
    }

    // --- Phase B: mma mainloop ---
    int warp = tid >> 5;
    int lane = tid & 31;
    int g = lane >> 2;
    int t = lane & 3;
    int n0 = warp * 16;

    float acc[8][4];
#pragma unroll
    for (int tl = 0; tl < 8; tl++)
#pragma unroll
        for (int r = 0; r < 4; r++) acc[tl][r] = 0.f;

#pragma unroll 4
    for (int ks = 0; ks < 16; ks++) {
        int k0 = ks * 8;
        const float* xb = Xs + (n0 + g) * GSTR + k0;
        float a0 = xb[t];
        float a1 = xb[8 * GSTR + t];
        float a2 = xb[t + 4];
        float a3 = xb[8 * GSTR + t + 4];
        unsigned ahi[4], alo[4];
        split_tf32(a0, ahi[0], alo[0]);
        split_tf32(a1, ahi[1], alo[1]);
        split_tf32(a2, ahi[2], alo[2]);
        split_tf32(a3, ahi[3], alo[3]);
#pragma unroll
        for (int tl = 0; tl < 8; tl++) {
            int wrow = (tl * 8 + g) * GSTR + k0;
            unsigned bh0 = __float_as_uint(Whi[wrow + t]);
            unsigned bh1 = __float_as_uint(Whi[wrow + t + 4]);
            unsigned bl0 = __float_as_uint(Wlo[wrow + t]);
            unsigned bl1 = __float_as_uint(Wlo[wrow + t + 4]);
            mma_tf32(acc[tl], ahi, bh0, bh1);
            mma_tf32(acc[tl], ahi, bl0, bl1);
            mma_tf32(acc[tl], alo, bh0, bh1);
        }
    }

    // --- Epilogue ---
    int nodeA = node0 + n0 + g;
    int nodeB = nodeA + 8;
#pragma unroll
    for (int tl = 0; tl < 8; tl++) {
        int o0 = tl * 8 + 2 * t;
        float bx = b[o0], by = b[o0 + 1];
        if (nodeA < N_NODES)
            *(float2*)(out + (long long)nodeA * F + o0) =
                make_float2(acc[tl][0] + bx, acc[tl][1] + by);
        if (nodeB < N_NODES)
            *(float2*)(out + (long long)nodeB * F + o0) =
                make_float2(acc[tl][2] + bx, acc[tl][3] + by);
    }
}

// ---------------------------------------------------------------------------
extern "C" void kernel_launch(void* const* d_in, const int* in_sizes, int n_in,
                              void* d_out, int out_size) {
    const float* h   = (const float*)d_in[0];
    const float* W   = (const float*)d_in[1];
    const float* b   = (const float*)d_in[2];
    const int*   src = (const int*)d_in[3];
    const int*   dst = (const int*)d_in[4];
    float* out = (float*)d_out;

    cudaFuncSetAttribute(gemm_kernel, cudaFuncAttributeMaxDynamicSharedMemorySize,
                         GEMM_SMEM_BYTES);

    hist_kernel<<<(N_EDGES / 4 + 255) / 256, 256>>>(dst);
    scan1_kernel<<<SCAN_NBLK, SCAN_BLOCK>>>();
    fill_kernel<<<(N_EDGES / 4 + 255) / 256, 256>>>(src, dst);
    gemm_kernel<<<(N_NODES + NT - 1) / NT, 128, GEMM_SMEM_BYTES>>>(h, W, b, out);
}

// round 8
// speedup vs baseline: 1.6360x; 1.6360x over previous
#include <cuda_runtime.h>
#include <cstdint>

#define N_NODES 100000
#define N_EDGES 1250000
#define F 64
#define K_DIM 128

// ---------------- device scratch ----------------
__device__ int g_count[N_NODES];     // in-degree (re-zeroed by gemm tail)
__device__ int g_cursor[N_NODES];    // block-LOCAL excl offset; fill bumps it
__device__ int g_esrc[N_EDGES];      // src ids grouped by dst

#define SCAN_BLOCK 1024
#define SCAN_NBLK 98                 // ceil(100000/1024)
__device__ int g_bsum[SCAN_NBLK];    // per-scan-block edge totals

// W tf32-splits, pre-swizzled to mma B-fragment layout:
// g_wsplit[(ks*8 + tl)*32 + lane] = {bh0, bh1, bl0, bl1}
__device__ uint4 g_wsplit[16 * 8 * 32];

__device__ __forceinline__ void split_tf32(float x, unsigned& hi, unsigned& lo) {
    unsigned h;
    asm("cvt.rna.tf32.f32 %0, %1;" : "=r"(h) : "f"(x));
    float r = x - __uint_as_float(h);
    asm("cvt.rna.tf32.f32 %0, %1;" : "=r"(lo) : "f"(r));
    hi = h;
}

__device__ __forceinline__ void mma_tf32(float d[4], const unsigned a[4],
                                         unsigned b0, unsigned b1) {
    asm volatile(
        "mma.sync.aligned.m16n8k8.row.col.f32.tf32.tf32.f32 "
        "{%0,%1,%2,%3}, {%4,%5,%6,%7}, {%8,%9}, {%0,%1,%2,%3};\n"
        : "+f"(d[0]), "+f"(d[1]), "+f"(d[2]), "+f"(d[3])
        : "r"(a[0]), "r"(a[1]), "r"(a[2]), "r"(a[3]), "r"(b0), "r"(b1));
}

// ---------------------------------------------------------------------------
// 1) histogram of dst, 4 edges/thread.
// ---------------------------------------------------------------------------
__global__ void hist_kernel(const int* __restrict__ dst) {
    int i = blockIdx.x * blockDim.x + threadIdx.x;
    if (i >= N_EDGES / 4) return;
    int4 d = ((const int4*)dst)[i];
    if ((unsigned)d.x < N_NODES) atomicAdd(&g_count[d.x], 1);
    if ((unsigned)d.y < N_NODES) atomicAdd(&g_count[d.y], 1);
    if ((unsigned)d.z < N_NODES) atomicAdd(&g_count[d.z], 1);
    if ((unsigned)d.w < N_NODES) atomicAdd(&g_count[d.w], 1);
}

// ---------------------------------------------------------------------------
// 2) scan1 + W-split prep in one grid. Blocks [0,98): block-local exclusive
//    scan of g_count -> g_cursor (local), totals -> g_bsum. Blocks [98,102):
//    build g_wsplit fragments (needs only W).
// ---------------------------------------------------------------------------
__global__ __launch_bounds__(SCAN_BLOCK) void scan_prep_kernel(const float* __restrict__ W) {
    if (blockIdx.x >= SCAN_NBLK) {
        int idx = (blockIdx.x - SCAN_NBLK) * SCAN_BLOCK + threadIdx.x;  // 0..4095
        if (idx < 16 * 8 * 32) {
            int lane = idx & 31;
            int tl = (idx >> 5) & 7;
            int ks = idx >> 8;
            int g = lane >> 2, t = lane & 3;
            int o = tl * 8 + g;
            int k0 = ks * 8;
            float w0 = W[o * K_DIM + k0 + t];
            float w1 = W[o * K_DIM + k0 + t + 4];
            unsigned h0, l0, h1, l1;
            split_tf32(w0, h0, l0);
            split_tf32(w1, h1, l1);
            g_wsplit[idx] = make_uint4(h0, h1, l0, l1);
        }
        return;
    }
    __shared__ int wsum[32];
    int tid = threadIdx.x;
    int lane = tid & 31, wid = tid >> 5;
    int i = blockIdx.x * SCAN_BLOCK + tid;
    int v = (i < N_NODES) ? g_count[i] : 0;

    int inc = v;
#pragma unroll
    for (int d = 1; d < 32; d <<= 1) {
        int t = __shfl_up_sync(0xffffffffu, inc, d);
        if (lane >= d) inc += t;
    }
    if (lane == 31) wsum[wid] = inc;
    __syncthreads();
    if (wid == 0) {
        int wv = wsum[lane];
        int winc = wv;
#pragma unroll
        for (int d = 1; d < 32; d <<= 1) {
            int t = __shfl_up_sync(0xffffffffu, winc, d);
            if (lane >= d) winc += t;
        }
        wsum[lane] = winc - wv;
    }
    __syncthreads();
    int excl = (inc - v) + wsum[wid];
    if (i < N_NODES) g_cursor[i] = excl;
    if (tid == SCAN_BLOCK - 1) g_bsum[blockIdx.x] = excl + v;
}

// ---------------------------------------------------------------------------
// 3) bucket fill, 4 edges/thread; 98-entry cross-block prefix built in smem.
// ---------------------------------------------------------------------------
__global__ __launch_bounds__(256) void fill_kernel(const int* __restrict__ src,
                                                   const int* __restrict__ dst) {
    __shared__ int sb[SCAN_NBLK];
    __shared__ int sp[SCAN_NBLK];
    int tid = threadIdx.x;
    if (tid < SCAN_NBLK) sb[tid] = g_bsum[tid];
    __syncthreads();
    if (tid < SCAN_NBLK) {
        int a = 0;
        for (int j = 0; j < tid; j++) a += sb[j];
        sp[tid] = a;
    }
    __syncthreads();

    int i = blockIdx.x * blockDim.x + tid;
    if (i >= N_EDGES / 4) return;
    int4 s4 = ((const int4*)src)[i];
    int4 d4 = ((const int4*)dst)[i];
#pragma unroll
    for (int j = 0; j < 4; j++) {
        int d = (j == 0) ? d4.x : (j == 1) ? d4.y : (j == 2) ? d4.z : d4.w;
        int s = (j == 0) ? s4.x : (j == 1) ? s4.y : (j == 2) ? s4.z : s4.w;
        if ((unsigned)d < N_NODES) {
            int pos = sp[d >> 10] + atomicAdd(&g_cursor[d], 1);
            if ((unsigned)pos < N_EDGES)
                g_esrc[pos] = ((unsigned)s < N_NODES) ? s : 0;
        }
    }
}

// ---------------------------------------------------------------------------
// 4) fused aggregate + tensor-core GEMM (3xTF32). Smem = Xs ONLY (33.8 KB)
//    -> 6 blocks/SM, 24 warps/SM. W fragments come from g_wsplit via one
//    coalesced LDG.128 per (ks, tl), L1/L2-hot.
// ---------------------------------------------------------------------------
#define NT 64
#define GSTR 132

__global__ __launch_bounds__(128) void gemm_kernel(const float* __restrict__ h,
                                                   const float* __restrict__ b,
                                                   float* __restrict__ out) {
    __shared__ float Xs[NT * GSTR];        // 33,792 B
    __shared__ int s_base;

    int tid = threadIdx.x;
    int node0 = blockIdx.x * NT;
    int blk = node0 >> 10;                 // scan-block owning all 64 nodes

    // cross-scan-block base via parallel smem reduce (no serial LDG chain)
    if (tid == 0) s_base = 0;
    __syncthreads();
    if (tid < SCAN_NBLK && tid < blk) atomicAdd(&s_base, g_bsum[tid]);

    // --- Phase A2: self features (overlaps with the reduce) ---
    for (int idx = tid; idx < NT * 16; idx += 128) {
        int n = idx >> 4, q = idx & 15;
        int node = node0 + n;
        float4 v = make_float4(0.f, 0.f, 0.f, 0.f);
        if (node < N_NODES) v = ((const float4*)(h + (long long)node * F))[q];
        *(float4*)&Xs[n * GSTR + q * 4] = v;
    }
    __syncthreads();
    int base = s_base;

    // --- Phase A3: neighbor mean, half-warp per node ---
    {
        int hw = tid >> 4;
        int ln = tid & 15;
        for (int n = hw; n < NT; n += 8) {
            int node = node0 + n;
            float4 a = make_float4(0.f, 0.f, 0.f, 0.f);
            float inv = 0.f;
            if (node < N_NODES) {
                int deg = g_count[node];
                int off = base + g_cursor[node] - deg;  // cursor = local_excl + deg
                int e = 0;
                for (; e + 4 <= deg; e += 4) {
                    int s0 = g_esrc[off + e + 0];
                    int s1 = g_esrc[off + e + 1];
                    int s2 = g_esrc[off + e + 2];
                    int s3 = g_esrc[off + e + 3];
                    float4 v0 = ((const float4*)(h + (long long)s0 * F))[ln];
                    float4 v1 = ((const float4*)(h + (long long)s1 * F))[ln];
                    float4 v2 = ((const float4*)(h + (long long)s2 * F))[ln];
                    float4 v3 = ((const float4*)(h + (long long)s3 * F))[ln];
                    a.x += v0.x + v1.x + v2.x + v3.x;
                    a.y += v0.y + v1.y + v2.y + v3.y;
                    a.z += v0.z + v1.z + v2.z + v3.z;
                    a.w += v0.w + v1.w + v2.w + v3.w;
                }
                for (; e < deg; e++) {
                    int s = g_esrc[off + e];
                    float4 v = ((const float4*)(h + (long long)s * F))[ln];
                    a.x += v.x; a.y += v.y; a.z += v.z; a.w += v.w;
                }
                inv = 1.f / fmaxf((float)deg, 1.f);
            }
            *(float4*)&Xs[n * GSTR + 64 + ln * 4] =
                make_float4(a.x * inv, a.y * inv, a.z * inv, a.w * inv);
        }
    }
    __syncthreads();

    // --- tail: re-zero this block's g_count for the next replay ---
    for (int n = tid; n < NT; n += 128) {
        int node = node0 + n;
        if (node < N_NODES) g_count[node] = 0;
    }

    // --- Phase B: mma mainloop; W fragments via coalesced LDG.128 ---
    int warp = tid >> 5;
    int lane = tid & 31;
    int g = lane >> 2;
    int t = lane & 3;
    int n0 = warp * 16;

    float acc[8][4];
#pragma unroll
    for (int tl = 0; tl < 8; tl++)
#pragma unroll
        for (int r = 0; r < 4; r++) acc[tl][r] = 0.f;

#pragma unroll 4
    for (int ks = 0; ks < 16; ks++) {
        int k0 = ks * 8;
        const float* xb = Xs + (n0 + g) * GSTR + k0;
        float a0 = xb[t];
        float a1 = xb[8 * GSTR + t];
        float a2 = xb[t + 4];
        float a3 = xb[8 * GSTR + t + 4];
        unsigned ahi[4], alo[4];
        split_tf32(a0, ahi[0], alo[0]);
        split_tf32(a1, ahi[1], alo[1]);
        split_tf32(a2, ahi[2], alo[2]);
        split_tf32(a3, ahi[3], alo[3]);
        const uint4* wp = g_wsplit + ks * 8 * 32 + lane;
#pragma unroll
        for (int tl = 0; tl < 8; tl++) {
            uint4 wv = __ldg(wp + tl * 32);    // {bh0, bh1, bl0, bl1}
            mma_tf32(acc[tl], ahi, wv.x, wv.y);   // hi*hi
            mma_tf32(acc[tl], ahi, wv.z, wv.w);   // hi*lo
            mma_tf32(acc[tl], alo, wv.x, wv.y);   // lo*hi
        }
    }

    // --- Epilogue ---
    int nodeA = node0 + n0 + g;
    int nodeB = nodeA + 8;
#pragma unroll
    for (int tl = 0; tl < 8; tl++) {
        int o0 = tl * 8 + 2 * t;
        float bx = b[o0], by = b[o0 + 1];
        if (nodeA < N_NODES)
            *(float2*)(out + (long long)nodeA * F + o0) =
                make_float2(acc[tl][0] + bx, acc[tl][1] + by);
        if (nodeB < N_NODES)
            *(float2*)(out + (long long)nodeB * F + o0) =
                make_float2(acc[tl][2] + bx, acc[tl][3] + by);
    }
}

// ---------------------------------------------------------------------------
extern "C" void kernel_launch(void* const* d_in, const int* in_sizes, int n_in,
                              void* d_out, int out_size) {
    const float* h   = (const float*)d_in[0];
    const float* W   = (const float*)d_in[1];
    const float* b   = (const float*)d_in[2];
    const int*   src = (const int*)d_in[3];
    const int*   dst = (const int*)d_in[4];
    float* out = (float*)d_out;

    hist_kernel<<<(N_EDGES / 4 + 255) / 256, 256>>>(dst);
    scan_prep_kernel<<<SCAN_NBLK + 4, SCAN_BLOCK>>>(W);
    fill_kernel<<<(N_EDGES / 4 + 255) / 256, 256>>>(src, dst);
    gemm_kernel<<<(N_NODES + NT - 1) / NT, 128>>>(h, b, out);
}